// round 13
// baseline (speedup 1.0000x reference)
#include <cuda_runtime.h>
#include <cstdint>

#define B_DIM 512
#define IN_DIM 512
#define OUT_DIM 1024
#define TM 32
#define TN 64
#define TK 32
#define KSPL 256   // K per warp-group (half of IN_DIM)

// Tropical (min-plus) matmul: out[m, n] = min_k (x[m,k] + w[n,k])
// x: [512, 512], w: [1024, 512], out: [512, 1024], row-major fp32.
//
// Intra-CTA K-split: 256-thread CTA, two 128-thread groups compute the SAME
// 32x64 output tile over DIFFERENT K-halves. Grid (16,16) = 256 CTAs x 8
// warps for latency hiding. Groups synchronize their own double-buffered
// mainloops with NAMED barriers (bar.sync 1/2, 128) so the halves don't
// couple; the in-CTA cross-split min reduction at the end uses two
// __syncthreads and a dead smem region. No scratch, no fences, no tail.
//
// Inner-loop issue diet: the x tile is stored DUPLICATED as float2 {x,x}
// (swizzled at float2 granularity, col = m ^ (k&28)), so one LDS.128 yields
// two duplicated f32x2 operands in aligned register pairs — no MOV packs.
// Adds are add.rn.f32x2 (bit-identical to scalar FADD RN); mins are scalar
// FMNMX on the (directly addressable) halves of the packed sums.

__device__ __forceinline__ unsigned long long pack2(float lo, float hi) {
    unsigned long long r;
    asm("mov.b64 %0, {%1, %2};" : "=l"(r) : "r"(__float_as_uint(lo)), "r"(__float_as_uint(hi)));
    return r;
}
__device__ __forceinline__ unsigned long long addf32x2(unsigned long long a, unsigned long long b) {
    unsigned long long r;
    asm("add.rn.f32x2 %0, %1, %2;" : "=l"(r) : "l"(a), "l"(b));
    return r;
}
__device__ __forceinline__ void unpack2(unsigned long long v, float& lo, float& hi) {
    uint32_t l, h;
    asm("mov.b64 {%0, %1}, %2;" : "=r"(l), "=r"(h) : "l"(v));
    lo = __uint_as_float(l);
    hi = __uint_as_float(h);
}

__global__ __launch_bounds__(256, 2)
void tropical_mm_kernel(const float* __restrict__ x,
                        const float* __restrict__ w,
                        float* __restrict__ out)
{
    // Per-group tiles: [group][buffer][k][col]
    __shared__ float2 xs2[2][2][TK][TM];  // duplicated x: 32 KB total
    __shared__ float  ws [2][2][TK][TN];  // 32 KB total

    const int tid    = threadIdx.x;
    const int group  = tid >> 7;          // 0 or 1 = K-half
    const int wg_tid = tid & 127;
    const int tx = wg_tid & 15;           // n-group: 4 outputs -> 64
    const int ty = wg_tid >> 4;           // m-group: 4 outputs -> 32
    const int n0 = blockIdx.x * TN;
    const int m0 = blockIdx.y * TM;
    const int kb = group * KSPL;
    const int bar_id = group + 1;         // named barrier per group

    // Cooperative-load coords (float4 granularity) within the group
    const int lr = wg_tid >> 3;           // 0..15
    const int lk = (wg_tid & 7) << 2;     // 0,4,...,28

    const float* xg0 = &x[(m0 + lr) * IN_DIM + kb + lk];
    const float* wg0 = &w[(n0 + lr) * IN_DIM + kb + lk];

    const float INF = __int_as_float(0x7f800000);
    float acc[4][4];
#pragma unroll
    for (int i = 0; i < 4; i++)
#pragma unroll
        for (int j = 0; j < 4; j++) acc[i][j] = INF;

    // Prologue: first tile into registers
    float4 xa0 = *reinterpret_cast<const float4*>(xg0);
    float4 xa1 = *reinterpret_cast<const float4*>(xg0 + 16 * IN_DIM);
    float4 wa0 = *reinterpret_cast<const float4*>(wg0);
    float4 wa1 = *reinterpret_cast<const float4*>(wg0 + 16 * IN_DIM);
    float4 wa2 = *reinterpret_cast<const float4*>(wg0 + 32 * IN_DIM);
    float4 wa3 = *reinterpret_cast<const float4*>(wg0 + 48 * IN_DIM);

    int p = 0;
    for (int k0 = 0; k0 < KSPL; k0 += TK) {
        // STS current tile (swizzled, conflict-free). Columns computed as
        // (row ^ lk) directly — NO additive shortcuts (see R3 bug).
        // x stored duplicated {v,v} at float2 granularity.
        {
            int x0c = (lr +  0) ^ lk;
            int x1c = (lr + 16) ^ lk;
#pragma unroll
            for (int j = 0; j < 4; j++) {
                float v0 = (&xa0.x)[j];
                float v1 = (&xa1.x)[j];
                xs2[group][p][lk + j][x0c] = make_float2(v0, v0);
                xs2[group][p][lk + j][x1c] = make_float2(v1, v1);
            }
            int w0c = (lr +  0) ^ lk;
            int w1c = (lr + 16) ^ lk;
            int w2c = (lr + 32) ^ lk;
            int w3c = (lr + 48) ^ lk;
#pragma unroll
            for (int j = 0; j < 4; j++) {
                ws[group][p][lk + j][w0c] = (&wa0.x)[j];
                ws[group][p][lk + j][w1c] = (&wa1.x)[j];
                ws[group][p][lk + j][w2c] = (&wa2.x)[j];
                ws[group][p][lk + j][w3c] = (&wa3.x)[j];
            }
        }
        asm volatile("bar.sync %0, 128;" :: "r"(bar_id) : "memory");

        // Prefetch next tile (overlaps the 32-k compute loop)
        if (k0 + TK < KSPL) {
            xg0 += TK; wg0 += TK;
            xa0 = *reinterpret_cast<const float4*>(xg0);
            xa1 = *reinterpret_cast<const float4*>(xg0 + 16 * IN_DIM);
            wa0 = *reinterpret_cast<const float4*>(wg0);
            wa1 = *reinterpret_cast<const float4*>(wg0 + 16 * IN_DIM);
            wa2 = *reinterpret_cast<const float4*>(wg0 + 32 * IN_DIM);
            wa3 = *reinterpret_cast<const float4*>(wg0 + 48 * IN_DIM);
        }

        // Compute: 8 k-classes x 4 k each; base pointers computed once per
        // class, inner LDS are [Rbase + immediate].
#pragma unroll
        for (int i = 0; i < 8; i++) {
            const float2* xp2 = &xs2[group][p][i << 2][(ty << 2) ^ (i << 2)];
            const float*  wp  = &ws [group][p][i << 2][(tx << 2) ^ (i << 2)];
#pragma unroll
            for (int kk = 0; kk < 4; kk++) {
                // (m0,m0),(m1,m1) and (m2,m2),(m3,m3): ready f32x2 operands
                ulonglong2 xq0 = *reinterpret_cast<const ulonglong2*>(xp2 + kk * TM);
                ulonglong2 xq1 = *reinterpret_cast<const ulonglong2*>(xp2 + kk * TM + 2);
                float4 wv = *reinterpret_cast<const float4*>(wp + kk * TN);
                unsigned long long w01 = pack2(wv.x, wv.y);   // aligned pair: free
                unsigned long long w23 = pack2(wv.z, wv.w);
                unsigned long long xd[4] = {xq0.x, xq0.y, xq1.x, xq1.y};
#pragma unroll
                for (int a = 0; a < 4; a++) {
                    unsigned long long s01 = addf32x2(xd[a], w01);
                    unsigned long long s23 = addf32x2(xd[a], w23);
                    float s0, s1, s2, s3;
                    unpack2(s01, s0, s1);                     // reg halves: free
                    unpack2(s23, s2, s3);
                    acc[a][0] = fminf(acc[a][0], s0);
                    acc[a][1] = fminf(acc[a][1], s1);
                    acc[a][2] = fminf(acc[a][2], s2);
                    acc[a][3] = fminf(acc[a][3], s3);
                }
            }
        }
        p ^= 1;
        // Single named barrier per tile: within a group, nobody overwrites
        // buffer q before passing the NEXT tile's barrier, by which time
        // every group thread finished computing from q. Groups independent.
    }

    // ── In-CTA cross-split reduction ─────────────────────────────────────
    // Reuse group 1's x-tile region (dead after the mainloop): 16 KB >= 8 KB.
    float (*red)[128] = reinterpret_cast<float (*)[128]>(&xs2[1][0][0][0]);

    __syncthreads();                     // both groups done with mainloop smem
    if (group == 1) {
#pragma unroll
        for (int i = 0; i < 4; i++)
#pragma unroll
            for (int j = 0; j < 4; j++)
                red[(i << 2) + j][wg_tid] = acc[i][j];
    }
    __syncthreads();                     // handoff visible

    if (group == 0) {
#pragma unroll
        for (int i = 0; i < 4; i++) {
#pragma unroll
            for (int j = 0; j < 4; j++)
                acc[i][j] = fminf(acc[i][j], red[(i << 2) + j][wg_tid]);
            float4 o = make_float4(acc[i][0], acc[i][1], acc[i][2], acc[i][3]);
            *reinterpret_cast<float4*>(
                &out[(m0 + (ty << 2) + i) * OUT_DIM + n0 + (tx << 2)]) = o;
        }
    }
}

extern "C" void kernel_launch(void* const* d_in, const int* in_sizes, int n_in,
                              void* d_out, int out_size)
{
    const float* x = (const float*)d_in[0];   // [512, 512]
    const float* w = (const float*)d_in[1];   // [1024, 512]
    float* out = (float*)d_out;               // [512, 1024]

    dim3 grid(OUT_DIM / TN, B_DIM / TM);      // (16, 16) = 256 CTAs x 256 thr
    tropical_mm_kernel<<<grid, 256>>>(x, w, out);
}

// round 14
// speedup vs baseline: 1.0938x; 1.0938x over previous
#include <cuda_runtime.h>
#include <cstdint>

#define B_DIM 512
#define IN_DIM 512
#define OUT_DIM 1024
#define TM 32
#define TN 64
#define TK 32
#define KSPL 256   // K per warp-group (half of IN_DIM)

// Tropical (min-plus) matmul: out[m, n] = min_k (x[m,k] + w[n,k])
// x: [512, 512], w: [1024, 512], out: [512, 1024], row-major fp32.
//
// Intra-CTA K-split: 256-thread CTA, two 128-thread groups compute the SAME
// 32x64 output tile over DIFFERENT K-halves. Grid (16,16) = 256 CTAs x 8
// warps (~14 warps/SM). Each group runs its own double-buffered mainloop
// synchronized by a NAMED barrier (bar.sync 1/2, 128) so the halves don't
// couple. In-CTA cross-split min reduction via a dead smem region + two
// __syncthreads. No scratch, no fences, no tail kernel.
//
// Inner loop (per 16 (add,min) pairs): 2 LDS.128 + 4 w-dup packs +
// 8 add.rn.f32x2 + 16 FMNMX. The x LDS.128 quad provides aligned register
// pairs (x0,x1),(x2,x3) used DIRECTLY as f32x2 operands (zero packs);
// only w needs (wb,wb) duplication. add.rn.f32x2 is bit-identical to
// scalar FADD RN, so rel_err stays exactly 0.

__device__ __forceinline__ unsigned long long dup2(float v) {
    unsigned long long r;
    asm("mov.b64 %0, {%1, %1};" : "=l"(r) : "r"(__float_as_uint(v)));
    return r;
}
__device__ __forceinline__ unsigned long long addf32x2(unsigned long long a, unsigned long long b) {
    unsigned long long r;
    asm("add.rn.f32x2 %0, %1, %2;" : "=l"(r) : "l"(a), "l"(b));
    return r;
}
__device__ __forceinline__ void unpack2(unsigned long long v, float& lo, float& hi) {
    uint32_t l, h;
    asm("mov.b64 {%0, %1}, %2;" : "=r"(l), "=r"(h) : "l"(v));
    lo = __uint_as_float(l);
    hi = __uint_as_float(h);
}

__global__ __launch_bounds__(256, 2)
void tropical_mm_kernel(const float* __restrict__ x,
                        const float* __restrict__ w,
                        float* __restrict__ out)
{
    // Per-group tiles: [group][buffer][k][col]  (16 KB + 32 KB = 48 KB)
    __shared__ float xs[2][2][TK][TM];
    __shared__ float ws[2][2][TK][TN];

    const int tid    = threadIdx.x;
    const int group  = tid >> 7;          // 0 or 1 = K-half
    const int wg_tid = tid & 127;
    const int tx = wg_tid & 15;           // n-group: 4 outputs -> 64
    const int ty = wg_tid >> 4;           // m-group: 4 outputs -> 32
    const int n0 = blockIdx.x * TN;
    const int m0 = blockIdx.y * TM;
    const int kb = group * KSPL;
    const int bar_id = group + 1;         // named barrier per group

    // Cooperative-load coords (float4 granularity) within the group
    const int lr = wg_tid >> 3;           // 0..15
    const int lk = (wg_tid & 7) << 2;     // 0,4,...,28

    const float* xg0 = &x[(m0 + lr) * IN_DIM + kb + lk];
    const float* wg0 = &w[(n0 + lr) * IN_DIM + kb + lk];

    const float INF = __int_as_float(0x7f800000);
    float acc[4][4];
#pragma unroll
    for (int i = 0; i < 4; i++)
#pragma unroll
        for (int j = 0; j < 4; j++) acc[i][j] = INF;

    // Prologue: first tile into registers
    float4 xa0 = *reinterpret_cast<const float4*>(xg0);
    float4 xa1 = *reinterpret_cast<const float4*>(xg0 + 16 * IN_DIM);
    float4 wa0 = *reinterpret_cast<const float4*>(wg0);
    float4 wa1 = *reinterpret_cast<const float4*>(wg0 + 16 * IN_DIM);
    float4 wa2 = *reinterpret_cast<const float4*>(wg0 + 32 * IN_DIM);
    float4 wa3 = *reinterpret_cast<const float4*>(wg0 + 48 * IN_DIM);

    int p = 0;
    for (int k0 = 0; k0 < KSPL; k0 += TK) {
        // STS current tile (swizzled, conflict-free). Columns computed as
        // (row ^ lk) directly — NO additive shortcuts (see R3 bug).
        {
            int x0c = (lr +  0) ^ lk;
            int x1c = (lr + 16) ^ lk;
#pragma unroll
            for (int j = 0; j < 4; j++) {
                xs[group][p][lk + j][x0c] = (&xa0.x)[j];
                xs[group][p][lk + j][x1c] = (&xa1.x)[j];
            }
            int w0c = (lr +  0) ^ lk;
            int w1c = (lr + 16) ^ lk;
            int w2c = (lr + 32) ^ lk;
            int w3c = (lr + 48) ^ lk;
#pragma unroll
            for (int j = 0; j < 4; j++) {
                ws[group][p][lk + j][w0c] = (&wa0.x)[j];
                ws[group][p][lk + j][w1c] = (&wa1.x)[j];
                ws[group][p][lk + j][w2c] = (&wa2.x)[j];
                ws[group][p][lk + j][w3c] = (&wa3.x)[j];
            }
        }
        asm volatile("bar.sync %0, 128;" :: "r"(bar_id) : "memory");

        // Prefetch next tile (overlaps the 32-k compute loop)
        if (k0 + TK < KSPL) {
            xg0 += TK; wg0 += TK;
            xa0 = *reinterpret_cast<const float4*>(xg0);
            xa1 = *reinterpret_cast<const float4*>(xg0 + 16 * IN_DIM);
            wa0 = *reinterpret_cast<const float4*>(wg0);
            wa1 = *reinterpret_cast<const float4*>(wg0 + 16 * IN_DIM);
            wa2 = *reinterpret_cast<const float4*>(wg0 + 32 * IN_DIM);
            wa3 = *reinterpret_cast<const float4*>(wg0 + 48 * IN_DIM);
        }

        // Compute: 8 k-classes x 4 k each; base pointers computed once per
        // class, inner LDS are [Rbase + immediate].
#pragma unroll
        for (int i = 0; i < 8; i++) {
            const float* xp = &xs[group][p][i << 2][(ty << 2) ^ (i << 2)];
            const float* wp = &ws[group][p][i << 2][(tx << 2) ^ (i << 2)];
#pragma unroll
            for (int kk = 0; kk < 4; kk++) {
                float4 xv = *reinterpret_cast<const float4*>(xp + kk * TM);
                float4 wv = *reinterpret_cast<const float4*>(wp + kk * TN);
                // Aligned halves of the x quad are ready f32x2 operands:
                unsigned long long x01 =
                    reinterpret_cast<const unsigned long long*>(&xv)[0]; // (x0,x1)
                unsigned long long x23 =
                    reinterpret_cast<const unsigned long long*>(&xv)[1]; // (x2,x3)
#pragma unroll
                for (int b = 0; b < 4; b++) {
                    unsigned long long wd = dup2((&wv.x)[b]);   // (wb, wb)
                    unsigned long long s01 = addf32x2(x01, wd); // (x0+wb, x1+wb)
                    unsigned long long s23 = addf32x2(x23, wd); // (x2+wb, x3+wb)
                    float s0, s1, s2, s3;
                    unpack2(s01, s0, s1);   // register halves: free
                    unpack2(s23, s2, s3);
                    acc[0][b] = fminf(acc[0][b], s0);
                    acc[1][b] = fminf(acc[1][b], s1);
                    acc[2][b] = fminf(acc[2][b], s2);
                    acc[3][b] = fminf(acc[3][b], s3);
                }
            }
        }
        p ^= 1;
        // Single named barrier per tile: within a group, nobody overwrites
        // buffer q before passing the NEXT tile's barrier, by which time
        // every group thread finished computing from q. Groups independent.
    }

    // ── In-CTA cross-split reduction ─────────────────────────────────────
    // Reuse group 1's x-tile region (dead after the mainloop) as the
    // 16x128 handoff buffer: 16*128*4 = 8192 B == sizeof(xs[1]).
    float (*red)[128] = reinterpret_cast<float (*)[128]>(&xs[1][0][0][0]);

    __syncthreads();                     // both groups done with mainloop smem
    if (group == 1) {
#pragma unroll
        for (int i = 0; i < 4; i++)
#pragma unroll
            for (int j = 0; j < 4; j++)
                red[(i << 2) + j][wg_tid] = acc[i][j];
    }
    __syncthreads();                     // handoff visible

    if (group == 0) {
#pragma unroll
        for (int i = 0; i < 4; i++) {
#pragma unroll
            for (int j = 0; j < 4; j++)
                acc[i][j] = fminf(acc[i][j], red[(i << 2) + j][wg_tid]);
            float4 o = make_float4(acc[i][0], acc[i][1], acc[i][2], acc[i][3]);
            *reinterpret_cast<float4*>(
                &out[(m0 + (ty << 2) + i) * OUT_DIM + n0 + (tx << 2)]) = o;
        }
    }
}

extern "C" void kernel_launch(void* const* d_in, const int* in_sizes, int n_in,
                              void* d_out, int out_size)
{
    const float* x = (const float*)d_in[0];   // [512, 512]
    const float* w = (const float*)d_in[1];   // [1024, 512]
    float* out = (float*)d_out;               // [512, 1024]

    dim3 grid(OUT_DIM / TN, B_DIM / TM);      // (16, 16) = 256 CTAs x 256 thr
    tropical_mm_kernel<<<grid, 256>>>(x, w, out);
}